// round 10
// baseline (speedup 1.0000x reference)
#include <cuda_runtime.h>
#include <cstdint>
#include <type_traits>

namespace {

using u64 = unsigned long long;

constexpr int LD  = 9;     // 2*lambd+1
constexpr int NP  = 61;    // valid (mu,m1) / (mup,m1p) pairs
constexpr int BLK = 64;    // samples per block
constexpr int THR = 128;   // 2 threads per sample (mu-split)
constexpr int T4  = BLK * 81 / 4;  // 1296 float4 per tile

__host__ __device__ constexpr int imax(int a, int b) { return a > b ? a : b; }
__host__ __device__ constexpr int imin(int a, int b) { return a < b ? a : b; }

__host__ __device__ constexpr int lo_m(int m2) { return imax(0, 4 - m2); }
__host__ __device__ constexpr int hi_m(int m2) { return imin(8, 12 - m2); }

__host__ __device__ constexpr int cntmu(int mu) { return 9 - (mu >= 4 ? mu - 4 : 4 - mu); }
__host__ __device__ constexpr int ofsmu(int mu) {
    int o = 0;
    for (int i = 0; i < mu; i++) o += cntmu(i);
    return o;
}
// pair index for (m1,m2): mu-major, m1 ascending (matches reference enumeration)
__host__ __device__ constexpr int pidx(int m1, int m2) {
    int mu   = m1 + m2 - 4;
    int m1lo = imax(0, mu - 4);
    return ofsmu(mu) + (m1 - m1lo);
}
__host__ __device__ constexpr bool vmu(int m1) { return m1 >= 0 && m1 <= 8; }

template <int S, int E, class F>
__device__ __forceinline__ void static_for(F&& f) {
    if constexpr (S < E) {
        f(std::integral_constant<int, S>{});
        static_for<S + 1, E>(f);
    }
}

// ---- f32x2 dual-FMA plumbing (FFMA2 only reachable via PTX) ----
__device__ __forceinline__ u64 pk(float lo, float hi) {
    u64 r; asm("mov.b64 %0,{%1,%2};" : "=l"(r) : "f"(lo), "f"(hi)); return r;
}
__device__ __forceinline__ float lo32(u64 v) { return __int_as_float((int)v); }
__device__ __forceinline__ float hi32(u64 v) { return __int_as_float((int)(v >> 32)); }
__device__ __forceinline__ u64 mul2(u64 a, u64 b) {
    u64 r; asm("mul.rn.f32x2 %0,%1,%2;" : "=l"(r) : "l"(a), "l"(b)); return r;
}
__device__ __forceinline__ u64 fma2(u64 a, u64 b, u64 c) {
    u64 r; asm("fma.rn.f32x2 %0,%1,%2,%3;" : "=l"(r) : "l"(a), "l"(b), "l"(c)); return r;
}

__device__ __forceinline__ uint32_t smem_u32(const void* p) {
    uint32_t a;
    asm("{ .reg .u64 t; cvta.to.shared.u64 t, %1; cvt.u32.u64 %0, t; }" : "=r"(a) : "l"(p));
    return a;
}
// 16B async copy, src_size 0 -> zero-fill (branch-free tail handling)
__device__ __forceinline__ void cp16(uint32_t dst, const float4* src, int sz) {
    asm volatile("cp.async.cg.shared.global [%0], [%1], 16, %2;\n"
                 :: "r"(dst), "l"(src), "r"(sz));
}

// One role: mu rows paired as (PA,PA+1), (PB,PB+1), plus optional scalar row SR.
// For each m2: t-pairs t[k] = {uA*X1[m1A][k], uB*X1[m1B][k]} (invalid lane = 0),
// then per q: g2 = {v,v}*{x2,x2}, one FFMA2 per pair-row. All indices compile-time.
// Contains one __syncthreads (matched across both role branches, R9-proven) so the
// x1 tile can be reused as the output staging buffer.
template <int PA, int PB, int SR>
__device__ __forceinline__ void compute_role(const float* __restrict__ x1t,
                                             const float* __restrict__ x2t,
                                             const float* __restrict__ us,
                                             const u64*  __restrict__ vdup,
                                             float* __restrict__ stage) {
    u64 accA[9], accB[9];
    float accS[9];
#pragma unroll
    for (int i = 0; i < 9; i++) { accA[i] = 0ull; accB[i] = 0ull; accS[i] = 0.0f; }

    static_for<0, 9>([&](auto M2c) {
        constexpr int m2 = decltype(M2c)::value;

        float x2r[LD];
        static_for<0, LD>([&](auto Jc) {
            constexpr int j = decltype(Jc)::value;
            x2r[j] = x2t[m2 * LD + j];                    // conflict-free LDS
        });

        constexpr int  a0 = PA + 4 - m2, a1 = a0 + 1;
        constexpr int  b0 = PB + 4 - m2, b1 = b0 + 1;
        constexpr bool vA0 = vmu(a0), vA1 = vmu(a1), anyA = vA0 || vA1;
        constexpr bool vB0 = vmu(b0), vB1 = vmu(b1), anyB = vB0 || vB1;
        constexpr int  s0 = (SR >= 0) ? (SR + 4 - m2) : -1;
        constexpr bool vS = (SR >= 0) && vmu(s0);

        u64 tA[9], tB[9];
        float tS[9];
        if constexpr (anyA) {
            float ua0, ua1;
            if constexpr (vA0) ua0 = us[pidx(a0, m2)]; else ua0 = 0.0f;
            if constexpr (vA1) ua1 = us[pidx(a1, m2)]; else ua1 = 0.0f;
            const u64 u2 = pk(ua0, ua1);
            static_for<0, 9>([&](auto Kc) {
                constexpr int k = decltype(Kc)::value;
                float xa, xb;
                if constexpr (vA0) xa = x1t[a0 * 9 + k]; else xa = 0.0f;
                if constexpr (vA1) xb = x1t[a1 * 9 + k]; else xb = 0.0f;
                tA[k] = mul2(pk(xa, xb), u2);
            });
        }
        if constexpr (anyB) {
            float ub0, ub1;
            if constexpr (vB0) ub0 = us[pidx(b0, m2)]; else ub0 = 0.0f;
            if constexpr (vB1) ub1 = us[pidx(b1, m2)]; else ub1 = 0.0f;
            const u64 u2 = pk(ub0, ub1);
            static_for<0, 9>([&](auto Kc) {
                constexpr int k = decltype(Kc)::value;
                float xa, xb;
                if constexpr (vB0) xa = x1t[b0 * 9 + k]; else xa = 0.0f;
                if constexpr (vB1) xb = x1t[b1 * 9 + k]; else xb = 0.0f;
                tB[k] = mul2(pk(xa, xb), u2);
            });
        }
        if constexpr (vS) {
            const float uS = us[pidx(s0, m2)];
            static_for<0, 9>([&](auto Kc) {
                constexpr int k = decltype(Kc)::value;
                tS[k] = uS * x1t[s0 * 9 + k];
            });
        }

        static_for<0, 9>([&](auto Jc) {
            constexpr int m2p = decltype(Jc)::value;
            const u64 x2d = pk(x2r[m2p], x2r[m2p]);
            static_for<lo_m(m2p), hi_m(m2p) + 1>([&](auto Ic) {
                constexpr int m1p = decltype(Ic)::value;
                constexpr int q   = pidx(m1p, m2p);
                constexpr int mup = m1p + m2p - 4;
                const u64 g2 = mul2(vdup[q], x2d);        // {v*x2, v*x2}
                if constexpr (anyA) accA[mup] = fma2(tA[m1p], g2, accA[mup]);
                if constexpr (anyB) accB[mup] = fma2(tB[m1p], g2, accB[mup]);
                if constexpr (vS)   accS[mup] = fmaf(tS[m1p], lo32(g2), accS[mup]);
            });
        });
    });

    __syncthreads();   // all compute reads of x1s/x2s done (matched in both roles)

    static_for<0, 9>([&](auto Mc) {
        constexpr int mup = decltype(Mc)::value;
        stage[PA * 9 + mup]       = lo32(accA[mup]);
        stage[(PA + 1) * 9 + mup] = hi32(accA[mup]);
        stage[PB * 9 + mup]       = lo32(accB[mup]);
        stage[(PB + 1) * 9 + mup] = hi32(accB[mup]);
        if constexpr (SR >= 0) stage[SR * 9 + mup] = accS[mup];
    });
}

__global__ void __launch_bounds__(THR, 4)
wigner_kernel(const float* __restrict__ X1,
              const float* __restrict__ X2,
              const float* __restrict__ mult,
              float* __restrict__ out, int n) {
    __shared__ __align__(16) float x1s[BLK * 81];
    __shared__ __align__(16) float x2s[BLK * 81];
    __shared__ float us[NP];
    __shared__ u64   vdup[NP];

    const int tid    = threadIdx.x;
    const int lane   = tid & (BLK - 1);
    const int role   = tid >> 6;          // 0: mu {0,1,2,3,8}, 1: mu {4,5,6,7}
    const int bstart = blockIdx.x * BLK;

    // Rank-1 refactorization of mult: mult[p*61+q] = c[p]*c[q]
    if (tid < NP) {
        us[tid] = mult[tid * NP] * (1.0f / mult[0]);
        const float v = mult[tid];
        vdup[tid] = pk(v, v);             // pre-duplicated for f32x2 ops
    }

    // Stage BOTH tiles via cp.async (independent 16B copies, single wait).
    {
        const int      gbase4 = bstart * 81 / 4;       // bstart*81 % 4 == 0 (BLK=64)
        const int      tot4   = n * 81 / 4;
        const float4*  s1     = reinterpret_cast<const float4*>(X1);
        const float4*  s2     = reinterpret_cast<const float4*>(X2);
        const uint32_t d1     = smem_u32(x1s);
        const uint32_t d2     = smem_u32(x2s);
#pragma unroll
        for (int k = 0; k < (T4 + THR - 1) / THR; k++) {
            const int idx = k * THR + tid;
            if (idx < T4) {
                const int sz = (gbase4 + idx < tot4) ? 16 : 0;  // tail -> zero-fill
                cp16(d1 + idx * 16, s1 + gbase4 + idx, sz);
                cp16(d2 + idx * 16, s2 + gbase4 + idx, sz);
            }
        }
        asm volatile("cp.async.commit_group;\n");
        asm volatile("cp.async.wait_group 0;\n" ::: "memory");
    }
    __syncthreads();

    {
        const float* __restrict__ x1t = x1s + lane * 81;
        const float* __restrict__ x2t = x2s + lane * 81;
        float* stage = x1s + lane * 81;   // x1 tile reused post-barrier (inside role fn)
        if (role == 0) compute_role<0, 2, 8>(x1t, x2t, us, vdup, stage);
        else           compute_role<4, 6, -1>(x1t, x2t, us, vdup, stage);
    }
    __syncthreads();

    // Coalesced float4 writeback of the assembled tile.
    {
        const float4* srcs   = reinterpret_cast<const float4*>(x1s);
        float4*       dsto   = reinterpret_cast<float4*>(out);
        const int     gbase4 = bstart * 81 / 4;
        const int     tot4   = n * 81 / 4;
#pragma unroll
        for (int k = 0; k < (T4 + THR - 1) / THR; k++) {
            const int idx = k * THR + tid;
            if (idx < T4 && gbase4 + idx < tot4) dsto[gbase4 + idx] = srcs[idx];
        }
    }
}

}  // namespace

extern "C" void kernel_launch(void* const* d_in, const int* in_sizes, int n_in,
                              void* d_out, int out_size) {
    const float* X1   = (const float*)d_in[0];
    const float* X2   = (const float*)d_in[1];
    const float* mult = (const float*)d_in[6];
    float*       out  = (float*)d_out;

    const int n      = in_sizes[0] / 81;
    const int blocks = (n + BLK - 1) / BLK;
    wigner_kernel<<<blocks, THR>>>(X1, X2, mult, out, n);
}

// round 11
// speedup vs baseline: 1.6925x; 1.6925x over previous
#include <cuda_runtime.h>
#include <cstdint>
#include <type_traits>

namespace {

constexpr int LD  = 9;     // 2*lambd+1
constexpr int NP  = 61;    // valid (mu,m1) / (mup,m1p) pairs
constexpr int BLK = 64;    // samples per block, 1 thread per sample
constexpr int T4  = BLK * 81 / 4;  // 1296 float4 per tile

__host__ __device__ constexpr int imax(int a, int b) { return a > b ? a : b; }
__host__ __device__ constexpr int imin(int a, int b) { return a < b ? a : b; }

__host__ __device__ constexpr int lo_m(int m2) { return imax(0, 4 - m2); }
__host__ __device__ constexpr int hi_m(int m2) { return imin(8, 12 - m2); }

__host__ __device__ constexpr int cntmu(int mu) { return 9 - (mu >= 4 ? mu - 4 : 4 - mu); }
__host__ __device__ constexpr int ofsmu(int mu) {
    int o = 0;
    for (int i = 0; i < mu; i++) o += cntmu(i);
    return o;
}
// pair index for (m1,m2): mu-major, m1 ascending (matches reference enumeration)
__host__ __device__ constexpr int pidx(int m1, int m2) {
    int mu   = m1 + m2 - 4;
    int m1lo = imax(0, mu - 4);
    return ofsmu(mu) + (m1 - m1lo);
}

template <int S, int E, class F>
__device__ __forceinline__ void static_for(F&& f) {
    if constexpr (S < E) {
        f(std::integral_constant<int, S>{});
        static_for<S + 1, E>(f);
    }
}

__device__ __forceinline__ uint32_t smem_u32(const void* p) {
    uint32_t a;
    asm("{ .reg .u64 t; cvta.to.shared.u64 t, %1; cvt.u32.u64 %0, t; }" : "=r"(a) : "l"(p));
    return a;
}
// 16B async copy, src_size 0 -> zero-fill (branch-free tail handling)
__device__ __forceinline__ void cp16(uint32_t dst, const float4* src, int sz) {
    asm volatile("cp.async.cg.shared.global [%0], [%1], 16, %2;\n"
                 :: "r"(dst), "l"(src), "r"(sz));
}

// One m2 pass with the FULL g vector (61 entries): t is built once per (m1,m2)
// and reused for all 61 FFMAs (R8's g-halves built every t twice — 549 extra
// FMUL + 549 extra LDS per sample). Register budget: acc81 + g61 + t9 + x2r9
// ~ 175 < 204 avail at launch_bounds(64,5) -> no spills, all compile-time idx.
template <int M2>
__device__ __forceinline__ void full_pass(const float* __restrict__ x1t,
                                          const float (&x2r)[LD],
                                          const float* __restrict__ us,
                                          const float* __restrict__ vs,
                                          float (&acc)[81]) {
    float g[NP];
    static_for<0, LD>([&](auto Jc) {
        constexpr int m2p = decltype(Jc)::value;
        static_for<lo_m(m2p), hi_m(m2p) + 1>([&](auto Ic) {
            constexpr int m1p = decltype(Ic)::value;
            g[pidx(m1p, m2p)] = vs[pidx(m1p, m2p)] * x2r[m2p];
        });
    });
    static_for<lo_m(M2), hi_m(M2) + 1>([&](auto Mc) {
        constexpr int m1 = decltype(Mc)::value;
        const float uu = us[pidx(m1, M2)];
        float t[LD];
        static_for<0, LD>([&](auto Kc) {
            constexpr int k = decltype(Kc)::value;
            t[k] = uu * x1t[m1 * LD + k];   // LDS, conflict-free (stride 81, odd)
        });
        static_for<0, LD>([&](auto Jc) {
            constexpr int m2p = decltype(Jc)::value;
            static_for<lo_m(m2p), hi_m(m2p) + 1>([&](auto Ic) {
                constexpr int m1p = decltype(Ic)::value;
                acc[(m1 + M2 - 4) * LD + (m1p + m2p - 4)] +=
                    t[m1p] * g[pidx(m1p, m2p)];
            });
        });
    });
}

__global__ void __launch_bounds__(BLK, 5)
wigner_kernel(const float* __restrict__ X1,
              const float* __restrict__ X2,
              const float* __restrict__ mult,
              float* __restrict__ out, int n) {
    __shared__ __align__(16) float x1s[BLK * 81];
    __shared__ __align__(16) float x2s[BLK * 81];
    __shared__ float us[NP];
    __shared__ float vs[NP];

    const int tid    = threadIdx.x;
    const int bstart = blockIdx.x * BLK;

    // Rank-1 refactorization of mult: mult[p*61+q] = c[p]*c[q]
    //   v[q] = mult[q], u[p] = mult[61p]/mult[0]
    if (tid < NP) {
        vs[tid] = mult[tid];
        us[tid] = mult[tid * NP] * (1.0f / mult[0]);
    }

    // Stage BOTH tiles via cp.async (independent 16B copies, single wait).
    {
        const int      gbase4 = bstart * 81 / 4;       // bstart*81 % 4 == 0 (BLK=64)
        const int      tot4   = n * 81 / 4;
        const float4*  s1     = reinterpret_cast<const float4*>(X1);
        const float4*  s2     = reinterpret_cast<const float4*>(X2);
        const uint32_t d1     = smem_u32(x1s);
        const uint32_t d2     = smem_u32(x2s);
#pragma unroll
        for (int k = 0; k < (T4 + BLK - 1) / BLK; k++) {   // 21 slots
            const int idx = k * BLK + tid;
            if (idx < T4) {
                const int sz = (gbase4 + idx < tot4) ? 16 : 0;  // tail -> zero-fill
                cp16(d1 + idx * 16, s1 + gbase4 + idx, sz);
                cp16(d2 + idx * 16, s2 + gbase4 + idx, sz);
            }
        }
        asm volatile("cp.async.commit_group;\n");
        asm volatile("cp.async.wait_group 0;\n" ::: "memory");
    }
    __syncthreads();

    float acc[81];
#pragma unroll
    for (int i = 0; i < 81; i++) acc[i] = 0.0f;

    {
        const float* __restrict__ x1t = x1s + tid * 81;
        const float* __restrict__ x2t = x2s + tid * 81;
        static_for<0, LD>([&](auto M2c) {
            constexpr int m2 = decltype(M2c)::value;
            float x2r[LD];
            static_for<0, LD>([&](auto Jc) {
                constexpr int j = decltype(Jc)::value;
                x2r[j] = x2t[m2 * LD + j];        // conflict-free LDS
            });
            full_pass<m2>(x1t, x2r, us, vs, acc);
        });
    }

    // Stage result in smem (x1 tile is dead) for fully coalesced float4 stores.
#pragma unroll
    for (int i = 0; i < 81; i++) x1s[tid * 81 + i] = acc[i];
    __syncthreads();
    {
        const float4* srcs   = reinterpret_cast<const float4*>(x1s);
        float4*       dsto   = reinterpret_cast<float4*>(out);
        const int     gbase4 = bstart * 81 / 4;
        const int     tot4   = n * 81 / 4;
#pragma unroll
        for (int k = 0; k < (T4 + BLK - 1) / BLK; k++) {
            const int idx = k * BLK + tid;
            if (idx < T4 && gbase4 + idx < tot4) dsto[gbase4 + idx] = srcs[idx];
        }
    }
}

}  // namespace

extern "C" void kernel_launch(void* const* d_in, const int* in_sizes, int n_in,
                              void* d_out, int out_size) {
    const float* X1   = (const float*)d_in[0];
    const float* X2   = (const float*)d_in[1];
    const float* mult = (const float*)d_in[6];
    float*       out  = (float*)d_out;

    const int n      = in_sizes[0] / 81;
    const int blocks = (n + BLK - 1) / BLK;
    wigner_kernel<<<blocks, BLK>>>(X1, X2, mult, out, n);
}